// round 13
// baseline (speedup 1.0000x reference)
#include <cuda_runtime.h>
#include <cuda_fp16.h>
#include <cstdint>

// ---------------- problem constants ----------------
#define T_STEPS 300
#define BATCH   256
#define HID     128
#define D_IN    700
#define KPAD    704
#define LAYERS  4
#define OUTD    20
#define M_TOTAL (T_STEPS * BATCH)   // 76800

#define OUT_OFF  0
#define MEM_OFF  (BATCH * OUTD)
#define SPK_OFF  (MEM_OFF + BATCH * (T_STEPS + 1) * HID)
#define NORM_OFF (SPK_OFF + BATCH * (T_STEPS + 1) * HID)

// ---------------- scratch (device globals; no allocations) ----------------
__device__ float g_xs[(size_t)LAYERS * M_TOTAL * HID];
__device__ float g_rates[LAYERS * BATCH * HID];
__device__ __align__(16) float g_fcT[LAYERS][HID][HID];

// B operands precomputed in mma-FRAGMENT-DIRECT layout (uint32 = 2 packed fp16).
// word index: ((((kt*2+ks)*2+c)*4+wn)*32+lane)*8 + nf*2+reg
// value: comp c of (W[k][n]*32, W[k+1][n]*32) with k = kt*32+ks*16+reg*8+(lane%4)*2,
//        n = wn*32+nf*8+lane/4   (m16n8k16 .row.col B-fragment mapping)
#define WFRAG_PER_KT 4096                    // 2ks*2c*4wn*32lane*8w
__device__ __align__(16) uint32_t g_wfrag[22 * WFRAG_PER_KT];          // 360KB*2
__device__ __align__(16) uint32_t g_afrag[LAYERS * 4 * WFRAG_PER_KT];  // 512KB

// ---------------- smem tile geometry (A only; 2 comps) ----------------
#define ROWB    80
#define CSTRIDE (128 * ROWB)       // 10240 per comp
#define ATILE   (2 * CSTRIDE)      // 20480: one 2-comp A tile (32 k)
#define FUSED_SMEM (4 * ATILE)     // 81920: phase-2 A resident (phase-1 uses regions 0,1)

// ---------------- helpers ----------------
__device__ __forceinline__ uint32_t smem_u32(const void* p) {
    uint32_t a;
    asm("{ .reg .u64 t; cvta.to.shared.u64 t, %1; cvt.u32.u64 %0, t; }" : "=r"(a) : "l"(p));
    return a;
}
__device__ __forceinline__ void ldsm4(uint32_t* d, uint32_t addr) {
    asm volatile("ldmatrix.sync.aligned.m8n8.x4.shared.b16 {%0,%1,%2,%3}, [%4];"
                 : "=r"(d[0]), "=r"(d[1]), "=r"(d[2]), "=r"(d[3]) : "r"(addr));
}
__device__ __forceinline__ void mma16816(float* d, const uint32_t* a, const uint32_t* b) {
    asm volatile(
        "mma.sync.aligned.m16n8k16.row.col.f32.f16.f16.f32 "
        "{%0,%1,%2,%3}, {%4,%5,%6,%7}, {%8,%9}, {%0,%1,%2,%3};"
        : "+f"(d[0]), "+f"(d[1]), "+f"(d[2]), "+f"(d[3])
        : "r"(a[0]), "r"(a[1]), "r"(a[2]), "r"(a[3]), "r"(b[0]), "r"(b[1]));
}
__device__ __forceinline__ void split2(float v, __half& c0, __half& c1) {
    c0 = __float2half_rn(v);
    c1 = __float2half_rn(v - __half2float(c0));
}
__device__ __forceinline__ uint32_t frag_word(float v0, float v1, int c) {
    __half a0, a1, b0, b1;
    split2(v0, a0, a1);
    split2(v1, b0, b1);
    __half lo = (c == 0) ? a0 : a1;
    __half hi = (c == 0) ? b0 : b1;
    return (uint32_t)__half_as_ushort(lo) | ((uint32_t)__half_as_ushort(hi) << 16);
}

// ============================================================
// A_norm = sum |A_w|
// ============================================================
__global__ __launch_bounds__(1024) void norm_kernel(const float* __restrict__ Aw,
                                                    float* __restrict__ dout) {
    __shared__ float s[1024];
    float acc = 0.f;
    const float4* A4 = (const float4*)Aw;
    const int N4 = LAYERS * HID * HID / 4;
    for (int i = threadIdx.x; i < N4; i += 1024) {
        float4 v = A4[i];
        acc += fabsf(v.x) + fabsf(v.y) + fabsf(v.z) + fabsf(v.w);
    }
    s[threadIdx.x] = acc;
    __syncthreads();
    for (int st = 512; st > 0; st >>= 1) {
        if (threadIdx.x < st) s[threadIdx.x] += s[threadIdx.x + st];
        __syncthreads();
    }
    if (threadIdx.x == 0) dout[NORM_OFF] = s[0];
}

// ============================================================
// presplit_w: w_in -> fragment-direct g_wfrag
// ============================================================
__global__ __launch_bounds__(256) void presplit_w(const float* __restrict__ w_in) {
    int i = blockIdx.x * 256 + threadIdx.x;
    if (i >= 22 * WFRAG_PER_KT) return;
    int w8 = i & 7, L = (i >> 3) & 31, wn = (i >> 8) & 3;
    int c = (i >> 10) & 1, ks = (i >> 11) & 1, kt = i >> 12;
    int nf = w8 >> 1, reg = w8 & 1;
    int k = kt * 32 + ks * 16 + reg * 8 + (L & 3) * 2;
    int n = wn * 32 + nf * 8 + (L >> 2);
    float v0 = (k < D_IN) ? w_in[(size_t)k * HID + n] * 32.f : 0.f;
    float v1 = (k + 1 < D_IN) ? w_in[(size_t)(k + 1) * HID + n] * 32.f : 0.f;
    g_wfrag[i] = frag_word(v0, v1, c);
}

// ============================================================
// presplit_A: A_w -> fragment-direct g_afrag ; fc_w transpose
// ============================================================
__global__ __launch_bounds__(256) void presplit_A(const float* __restrict__ Aw,
                                                  const float* __restrict__ fc_w) {
    int i = blockIdx.x * 256 + threadIdx.x;
    if (i < LAYERS * 4 * WFRAG_PER_KT) {
        int w8 = i & 7, L = (i >> 3) & 31, wn = (i >> 8) & 3;
        int c = (i >> 10) & 1, ks = (i >> 11) & 1, kt = (i >> 12) & 3, l = i >> 14;
        int nf = w8 >> 1, reg = w8 & 1;
        int k = kt * 32 + ks * 16 + reg * 8 + (L & 3) * 2;
        int n = wn * 32 + nf * 8 + (L >> 2);
        const float* A = Aw + (size_t)l * HID * HID;
        float v0 = A[(size_t)k * HID + n] * 32.f;
        float v1 = A[(size_t)(k + 1) * HID + n] * 32.f;
        g_afrag[i] = frag_word(v0, v1, c);
    }
    if (i < LAYERS * HID * HID) {
        int l = i >> 14, rem = i & 16383, n = rem >> 7, k = rem & 127;
        g_fcT[l][n][k] = fc_w[(size_t)l * HID * HID + (size_t)k * HID + n];
    }
}

// ============================================================
// MMA core: A from smem (ldsm), B fragments DIRECT from gmem (L2).
// Pass order unchanged: a0*b0 -> accA ; a0*b1, a1*b0 -> accB.
// ============================================================
__device__ __forceinline__ void tile_mma2(float (&accA)[2][4][4], float (&accB)[2][4][4],
                                          uint32_t Ab, const uint32_t* __restrict__ wf,
                                          uint32_t a_lane, int wn, int lane) {
#pragma unroll
    for (int ks = 0; ks < 2; ks++) {
        uint32_t bf[2][8];
#pragma unroll
        for (int c = 0; c < 2; c++) {
            const uint4* p = (const uint4*)(wf + (((size_t)(ks * 2 + c) * 4 + wn) * 32 + lane) * 8);
            uint4 v0 = __ldg(p), v1 = __ldg(p + 1);
            bf[c][0] = v0.x; bf[c][1] = v0.y; bf[c][2] = v0.z; bf[c][3] = v0.w;
            bf[c][4] = v1.x; bf[c][5] = v1.y; bf[c][6] = v1.z; bf[c][7] = v1.w;
        }
        uint32_t af[2][4];
#pragma unroll
        for (int mf = 0; mf < 2; mf++)
            ldsm4(af[mf], Ab + (uint32_t)(0 * CSTRIDE + mf * 16 * ROWB + ks * 32) + a_lane);
#pragma unroll
        for (int mf = 0; mf < 2; mf++)
#pragma unroll
            for (int nf = 0; nf < 4; nf++) mma16816(accA[mf][nf], af[mf], &bf[0][nf * 2]);
#pragma unroll
        for (int mf = 0; mf < 2; mf++)
#pragma unroll
            for (int nf = 0; nf < 4; nf++) mma16816(accB[mf][nf], af[mf], &bf[1][nf * 2]);
#pragma unroll
        for (int mf = 0; mf < 2; mf++)
            ldsm4(af[mf], Ab + (uint32_t)(1 * CSTRIDE + mf * 16 * ROWB + ks * 32) + a_lane);
#pragma unroll
        for (int mf = 0; mf < 2; mf++)
#pragma unroll
            for (int nf = 0; nf < 4; nf++) mma16816(accB[mf][nf], af[mf], &bf[0][nf * 2]);
    }
}

// ============================================================
// FUSED GEMM, grid=600, 512 threads:
//   phase 1: inp = x @ w_in + b_in (22 k-tiles; A staged+converted, B frag-direct)
//   epilogue: split2(inp*32) into smem A-resident layout (4 regions)
//   phase 2: xs[l] = inp @ A_w[l] + A_b[l] — ZERO barriers, B frag-direct
// ============================================================
__global__ __launch_bounds__(512, 1) void gemm_fused(const float* __restrict__ x,
                                                     const float* __restrict__ b_in,
                                                     const float* __restrict__ Abias) {
    extern __shared__ char smem[];
    const uint32_t sb = smem_u32(smem);
    const int tid = threadIdx.x, lane = tid & 31, wid = tid >> 5;
    const int wm = wid & 3, wn = wid >> 2;
    const int m0 = blockIdx.x * 128;
    const int q = lane >> 3, r = lane & 7;
    const uint32_t a_lane = (uint32_t)((wm * 32 + (q & 1) * 8 + r) * ROWB + ((q >> 1) * 8) * 2);
    const int srow = tid >> 2, skg = (tid & 3) * 8;

    float accA[2][4][4], accB[2][4][4];
#pragma unroll
    for (int i = 0; i < 2; i++)
#pragma unroll
        for (int j = 0; j < 4; j++)
#pragma unroll
            for (int k = 0; k < 4; k++) { accA[i][j][k] = 0.f; accB[i][j][k] = 0.f; }

    // ---------------- phase 1 ----------------
    float4 u0, u1;
    auto load_x = [&](int t) {
        const int k = t * 32 + skg;
        const float* p = x + (size_t)(m0 + srow) * D_IN + k;
        u0 = *(const float4*)p;
        u1 = (k + 4 < D_IN) ? *(const float4*)(p + 4) : make_float4(0.f, 0.f, 0.f, 0.f);
    };
    auto store_A = [&](int buf) {
        char* Abp = smem + buf * ATILE;
        float v[8] = {u0.x, u0.y, u0.z, u0.w, u1.x, u1.y, u1.z, u1.w};
        __align__(16) __half h0[8], h1[8];
#pragma unroll
        for (int j = 0; j < 8; j++) split2(v[j] * 32.f, h0[j], h1[j]);
        char* d = Abp + srow * ROWB + skg * 2;
        *(uint4*)(d + 0 * CSTRIDE) = *(uint4*)h0;
        *(uint4*)(d + 1 * CSTRIDE) = *(uint4*)h1;
    };

    load_x(0);
    store_A(0);
    __syncthreads();

    for (int t = 0; t < 22; t++) {
        const bool more = (t + 1) < 22;
        if (more) load_x(t + 1);
        tile_mma2(accA, accB, sb + (uint32_t)((t & 1) * ATILE),
                  g_wfrag + (size_t)t * WFRAG_PER_KT, a_lane, wn, lane);
        if (more) store_A((t + 1) & 1);
        __syncthreads();
    }

    // ---------------- epilogue 1: split inp into resident A layout ----------------
    {
        const float inv = 1.0f / 1024.0f;
#pragma unroll
        for (int mf = 0; mf < 2; mf++) {
            const int row0 = wm * 32 + mf * 16 + (lane >> 2);
#pragma unroll
            for (int nf = 0; nf < 4; nf++) {
                const int col = wn * 32 + nf * 8 + (lane & 3) * 2;
                const int kt = col >> 5, kk = col & 31;
                char* base = smem + kt * ATILE + kk * 2;
                const float bb0 = b_in[col], bb1 = b_in[col + 1];
#pragma unroll
                for (int hrow = 0; hrow < 2; hrow++) {
                    const int row = row0 + hrow * 8;
                    float va = (accA[mf][nf][hrow * 2 + 0] + accB[mf][nf][hrow * 2 + 0]) * inv + bb0;
                    float vb = (accA[mf][nf][hrow * 2 + 1] + accB[mf][nf][hrow * 2 + 1]) * inv + bb1;
                    va *= 32.f; vb *= 32.f;
                    __half a0, a1, b0, b1;
                    split2(va, a0, a1);
                    split2(vb, b0, b1);
                    char* d = base + row * ROWB;
                    *(__half2*)(d + 0 * CSTRIDE) = __halves2half2(a0, b0);
                    *(__half2*)(d + 1 * CSTRIDE) = __halves2half2(a1, b1);
                }
            }
        }
    }
    __syncthreads();

    // ---------------- phase 2: 4 layers x 4 k-tiles, NO barriers ----------------
#pragma unroll
    for (int i = 0; i < 2; i++)
#pragma unroll
        for (int j = 0; j < 4; j++)
#pragma unroll
            for (int k = 0; k < 4; k++) { accA[i][j][k] = 0.f; accB[i][j][k] = 0.f; }

    const float inv = 1.0f / 1024.0f;
    for (int s = 0; s < 16; s++) {
        const int l = s >> 2, kt = s & 3;
        tile_mma2(accA, accB, sb + (uint32_t)(kt * ATILE),
                  g_afrag + (size_t)s * WFRAG_PER_KT, a_lane, wn, lane);
        if (kt == 3) {
            float* dst = g_xs + (size_t)l * M_TOTAL * HID;
#pragma unroll
            for (int mf = 0; mf < 2; mf++) {
                const int row0 = m0 + wm * 32 + mf * 16 + (lane >> 2);
#pragma unroll
                for (int nf = 0; nf < 4; nf++) {
                    const int col = wn * 32 + nf * 8 + (lane & 3) * 2;
                    const float bb0 = Abias[l * HID + col];
                    const float bb1 = Abias[l * HID + col + 1];
                    *(float2*)(dst + (size_t)row0 * HID + col) =
                        make_float2((accA[mf][nf][0] + accB[mf][nf][0]) * inv + bb0,
                                    (accA[mf][nf][1] + accB[mf][nf][1]) * inv + bb1);
                    *(float2*)(dst + (size_t)(row0 + 8) * HID + col) =
                        make_float2((accA[mf][nf][2] + accB[mf][nf][2]) * inv + bb0,
                                    (accA[mf][nf][3] + accB[mf][nf][3]) * inv + bb1);
                }
            }
#pragma unroll
            for (int i = 0; i < 2; i++)
#pragma unroll
                for (int j = 0; j < 4; j++)
#pragma unroll
                    for (int k = 0; k < 4; k++) { accA[i][j][k] = 0.f; accB[i][j][k] = 0.f; }
        }
    }
}

// ============================================================
// Sequential LIF scan. block=(b,l), thread=h.
// ============================================================
__global__ void scan_kernel(const float* __restrict__ mem0,
                            const float* __restrict__ thr,
                            const float* __restrict__ decay,
                            const float* __restrict__ rstv,
                            float* __restrict__ dout) {
    const int b = blockIdx.x;
    const int l = blockIdx.y;
    const int h = threadIdx.x;

    const float* xp = g_xs + (size_t)l * M_TOTAL * HID + (size_t)b * T_STEPS * HID + h;
    float mem = mem0[(l * BATCH + b) * HID + h];
    float spk = 0.f, rate = 0.f;
    const float th = thr[h], dc = decay[h], rs = rstv[h];
    const bool last = (l == 3);

    float* mo = dout + MEM_OFF + (size_t)b * (T_STEPS + 1) * HID + h;
    float* so = dout + SPK_OFF + (size_t)b * (T_STEPS + 1) * HID + h;
    if (last) { mo[0] = mem; so[0] = 0.f; }

    for (int t = 0; t < T_STEPS; t += 10) {
        float v[10];
#pragma unroll
        for (int j = 0; j < 10; j++) v[j] = xp[(size_t)(t + j) * HID];
#pragma unroll
        for (int j = 0; j < 10; j++) {
            mem = rs * spk + mem * dc * (1.f - spk) + v[j];
            spk = (mem - th > 0.f) ? 1.f : 0.f;
            rate += spk;
            if (last) {
                mo[(size_t)(t + j + 1) * HID] = mem;
                so[(size_t)(t + j + 1) * HID] = spk;
            }
        }
    }
    g_rates[(l * BATCH + b) * HID + h] = rate * (1.f / 300.f);
}

// ============================================================
// Head: block per batch, 640 threads; fc_w pre-transposed.
// ============================================================
__global__ __launch_bounds__(640) void head_kernel(const float* __restrict__ fc_b,
                                                   const float* __restrict__ w_out,
                                                   const float* __restrict__ b_out,
                                                   float* __restrict__ dout) {
    const int b = blockIdx.x;
    const int tid = threadIdx.x;
    __shared__ float rs[512];
    __shared__ float cat[512];

    if (tid < 512) {
        int l = tid >> 7, h = tid & 127;
        rs[tid] = g_rates[(l * BATCH + b) * HID + h];
    }
    __syncthreads();

    if (tid < 512) {
        int l = tid >> 7, h = tid & 127;
        const float* W = &g_fcT[l][h][0];
        const float* rr = &rs[l * HID];
        float a0 = 0.f, a1 = 0.f, a2 = 0.f, a3 = 0.f;
#pragma unroll
        for (int k = 0; k < HID; k += 4) {
            float4 w4 = *(const float4*)(W + k);
            a0 += rr[k + 0] * w4.x;
            a1 += rr[k + 1] * w4.y;
            a2 += rr[k + 2] * w4.z;
            a3 += rr[k + 3] * w4.w;
        }
        float acc = ((a0 + a1) + (a2 + a3)) + fc_b[l * HID + h];
        cat[tid] = fmaxf(acc, 0.f);
    }
    __syncthreads();

    const int w = tid >> 5, lane = tid & 31;
    if (w < OUTD) {
        float acc = 0.f;
#pragma unroll
        for (int k = lane; k < 512; k += 32) acc += cat[k] * w_out[(size_t)k * OUTD + w];
#pragma unroll
        for (int off = 16; off; off >>= 1) acc += __shfl_down_sync(0xffffffffu, acc, off);
        if (lane == 0) dout[OUT_OFF + b * OUTD + w] = acc + b_out[w];
    }
}

// ============================================================
extern "C" void kernel_launch(void* const* d_in, const int* in_sizes, int n_in,
                              void* d_out, int out_size) {
    const float* x     = (const float*)d_in[0];
    const float* w_in  = (const float*)d_in[1];
    const float* b_in  = (const float*)d_in[2];
    const float* A_w   = (const float*)d_in[3];
    const float* A_b   = (const float*)d_in[4];
    const float* fc_w  = (const float*)d_in[5];
    const float* fc_b  = (const float*)d_in[6];
    const float* w_out = (const float*)d_in[7];
    const float* b_out = (const float*)d_in[8];
    const float* thr   = (const float*)d_in[9];
    const float* decay = (const float*)d_in[10];
    const float* rst   = (const float*)d_in[11];
    const float* mem0  = (const float*)d_in[12];
    float* out = (float*)d_out;

    cudaFuncSetAttribute(gemm_fused, cudaFuncAttributeMaxDynamicSharedMemorySize, FUSED_SMEM);

    // gemm_fused kept at launch index 3 for ncu capture
    norm_kernel<<<1, 1024>>>(A_w, out);
    presplit_w<<<(22 * WFRAG_PER_KT + 255) / 256, 256>>>(w_in);
    presplit_A<<<(LAYERS * 4 * WFRAG_PER_KT + 255) / 256, 256>>>(A_w, fc_w);
    gemm_fused<<<M_TOTAL / 128, 512, FUSED_SMEM>>>(x, b_in, A_b);

    dim3 g3(BATCH, LAYERS);
    scan_kernel<<<g3, 128>>>(mem0, thr, decay, rst, out);

    head_kernel<<<BATCH, 640>>>(fc_b, w_out, b_out, out);
}

// round 14
// speedup vs baseline: 1.0767x; 1.0767x over previous
#include <cuda_runtime.h>
#include <cuda_fp16.h>
#include <cstdint>

// ---------------- problem constants ----------------
#define T_STEPS 300
#define BATCH   256
#define HID     128
#define D_IN    700
#define KPAD    704
#define LAYERS  4
#define OUTD    20
#define M_TOTAL (T_STEPS * BATCH)   // 76800

#define OUT_OFF  0
#define MEM_OFF  (BATCH * OUTD)
#define SPK_OFF  (MEM_OFF + BATCH * (T_STEPS + 1) * HID)
#define NORM_OFF (SPK_OFF + BATCH * (T_STEPS + 1) * HID)

// ---------------- scratch (device globals; no allocations) ----------------
__device__ float g_xs[(size_t)LAYERS * M_TOTAL * HID];
__device__ float g_rates[LAYERS * BATCH * HID];
// presplit weights (scaled x32), 2 fp16 comps, [comp][n][k]
__device__ __align__(16) __half g_wsplit[2][HID][KPAD];
__device__ __align__(16) __half g_asplit[2][LAYERS][HID][HID];
__device__ __align__(16) float g_fcT[LAYERS][HID][HID];

// ---------------- smem tile geometry (BM=64) ----------------
#define ROWB    80
#define CSTA    (64 * ROWB)        // 5120: A comp stride (64 m-rows)
#define CSTB    (128 * ROWB)       // 10240: B comp stride (128 n-rows)
#define ATILE_A (2 * CSTA)         // 10240: one 2-comp A tile (32 k)
#define BTILE   (2 * CSTB)         // 20480: one 2-comp B tile (32 k)
#define BUF1    (ATILE_A + BTILE)  // 30720: phase-1 stage buffer
// phase-1: buffers at 0 and BUF1 (61440 total)
// phase-2: A-resident 4 kt at kt*ATILE_A (40960, overlays phase-1); B2 at 61440
#define B2OFF   (2 * BUF1)         // 61440
#define FUSED_SMEM (B2OFF + 2 * BTILE)  // 102400

// ---------------- helpers ----------------
__device__ __forceinline__ uint32_t smem_u32(const void* p) {
    uint32_t a;
    asm("{ .reg .u64 t; cvta.to.shared.u64 t, %1; cvt.u32.u64 %0, t; }" : "=r"(a) : "l"(p));
    return a;
}
__device__ __forceinline__ void ldsm4(uint32_t* d, uint32_t addr) {
    asm volatile("ldmatrix.sync.aligned.m8n8.x4.shared.b16 {%0,%1,%2,%3}, [%4];"
                 : "=r"(d[0]), "=r"(d[1]), "=r"(d[2]), "=r"(d[3]) : "r"(addr));
}
__device__ __forceinline__ void mma16816(float* d, const uint32_t* a, const uint32_t* b) {
    asm volatile(
        "mma.sync.aligned.m16n8k16.row.col.f32.f16.f16.f32 "
        "{%0,%1,%2,%3}, {%4,%5,%6,%7}, {%8,%9}, {%0,%1,%2,%3};"
        : "+f"(d[0]), "+f"(d[1]), "+f"(d[2]), "+f"(d[3])
        : "r"(a[0]), "r"(a[1]), "r"(a[2]), "r"(a[3]), "r"(b[0]), "r"(b[1]));
}
__device__ __forceinline__ void cpa16(uint32_t s, const void* g) {
    asm volatile("cp.async.cg.shared.global [%0], [%1], 16;" :: "r"(s), "l"(g));
}
__device__ __forceinline__ void cpa_wait_all() {
    asm volatile("cp.async.wait_all;" ::: "memory");
}
// 2-way fp16 split: residual <= 2^-25 |v| (fp32-class)
__device__ __forceinline__ void split2(float v, __half& c0, __half& c1) {
    c0 = __float2half_rn(v);
    c1 = __float2half_rn(v - __half2float(c0));
}

// ============================================================
// A_norm = sum |A_w|
// ============================================================
__global__ __launch_bounds__(1024) void norm_kernel(const float* __restrict__ Aw,
                                                    float* __restrict__ dout) {
    __shared__ float s[1024];
    float acc = 0.f;
    const float4* A4 = (const float4*)Aw;
    const int N4 = LAYERS * HID * HID / 4;
    for (int i = threadIdx.x; i < N4; i += 1024) {
        float4 v = A4[i];
        acc += fabsf(v.x) + fabsf(v.y) + fabsf(v.z) + fabsf(v.w);
    }
    s[threadIdx.x] = acc;
    __syncthreads();
    for (int st = 512; st > 0; st >>= 1) {
        if (threadIdx.x < st) s[threadIdx.x] += s[threadIdx.x + st];
        __syncthreads();
    }
    if (threadIdx.x == 0) dout[NORM_OFF] = s[0];
}

// ============================================================
// presplit_w: w_in -> 2 fp16 comps (x32), [n][k]
// ============================================================
__global__ __launch_bounds__(256) void presplit_w(const float* __restrict__ w_in) {
    int i = blockIdx.x * 256 + threadIdx.x;
    if (i < HID * KPAD) {
        int n = i / KPAD, k = i % KPAD;
        float v = (k < D_IN) ? w_in[(size_t)k * HID + n] * 32.f : 0.f;
        __half a, b;
        split2(v, a, b);
        g_wsplit[0][n][k] = a; g_wsplit[1][n][k] = b;
    }
}

// ============================================================
// presplit_A: A_w 2-comp split + fc_w transpose
// ============================================================
__global__ __launch_bounds__(256) void presplit_A(const float* __restrict__ Aw,
                                                  const float* __restrict__ fc_w) {
    int i = blockIdx.x * 256 + threadIdx.x;
    if (i < LAYERS * HID * HID) {
        int l = i >> 14, rem = i & 16383, n = rem >> 7, k = rem & 127;
        float v = Aw[(size_t)l * HID * HID + (size_t)k * HID + n] * 32.f;
        __half a, b;
        split2(v, a, b);
        g_asplit[0][l][n][k] = a; g_asplit[1][l][n][k] = b;
        g_fcT[l][n][k] = fc_w[(size_t)l * HID * HID + (size_t)k * HID + n];
    }
}

// ============================================================
// MMA core (warp tile 32x32), 3 passes:
//   accA += a0*b0 ; accB += a0*b1 + a1*b0
// A comps at stride CSTA, B comps at stride CSTB.
// ============================================================
__device__ __forceinline__ void tile_mma(float (&accA)[2][4][4], float (&accB)[2][4][4],
                                         uint32_t Ab, uint32_t Bb,
                                         uint32_t a_lane, uint32_t b_lane) {
#pragma unroll
    for (int ks = 0; ks < 2; ks++) {
        uint32_t bf[2][4][2];
#pragma unroll
        for (int c = 0; c < 2; c++)
#pragma unroll
            for (int np = 0; np < 2; np++) {
                uint32_t r4[4];
                ldsm4(r4, Bb + (uint32_t)(c * CSTB + np * 16 * ROWB + ks * 32) + b_lane);
                bf[c][np * 2 + 0][0] = r4[0]; bf[c][np * 2 + 0][1] = r4[1];
                bf[c][np * 2 + 1][0] = r4[2]; bf[c][np * 2 + 1][1] = r4[3];
            }
        uint32_t af[2][4];
#pragma unroll
        for (int mf = 0; mf < 2; mf++)
            ldsm4(af[mf], Ab + (uint32_t)(0 * CSTA + mf * 16 * ROWB + ks * 32) + a_lane);
#pragma unroll
        for (int mf = 0; mf < 2; mf++)
#pragma unroll
            for (int nf = 0; nf < 4; nf++) mma16816(accA[mf][nf], af[mf], bf[0][nf]);
#pragma unroll
        for (int mf = 0; mf < 2; mf++)
#pragma unroll
            for (int nf = 0; nf < 4; nf++) mma16816(accB[mf][nf], af[mf], bf[1][nf]);
#pragma unroll
        for (int mf = 0; mf < 2; mf++)
            ldsm4(af[mf], Ab + (uint32_t)(1 * CSTA + mf * 16 * ROWB + ks * 32) + a_lane);
#pragma unroll
        for (int mf = 0; mf < 2; mf++)
#pragma unroll
            for (int nf = 0; nf < 4; nf++) mma16816(accB[mf][nf], af[mf], bf[0][nf]);
    }
}

// ============================================================
// FUSED GEMM, BM=64, grid=1200, 256 threads (8 warps, 2x4 grid), 2 blocks/SM:
//   phase 1: inp = x @ w_in + b_in (22 k-tiles)
//   epilogue: split2(inp*32) direct to phase-2 smem A layout
//   phase 2: xs[l] = inp @ A_w[l] + A_b[l], 4 layers x 4 k-tiles
// ============================================================
__global__ __launch_bounds__(256, 2) void gemm_fused(const float* __restrict__ x,
                                                     const float* __restrict__ b_in,
                                                     const float* __restrict__ Abias) {
    extern __shared__ char smem[];
    const uint32_t sb = smem_u32(smem);
    const int tid = threadIdx.x, lane = tid & 31, wid = tid >> 5;
    const int wm = wid & 1, wn = wid >> 1;
    const int m0 = blockIdx.x * 64;
    const int q = lane >> 3, r = lane & 7;
    const uint32_t a_lane = (uint32_t)((wm * 32 + (q & 1) * 8 + r) * ROWB + ((q >> 1) * 8) * 2);
    const uint32_t b_lane = (uint32_t)((wn * 32 + (q >> 1) * 8 + r) * ROWB + ((q & 1) * 8) * 2);
    const int srow = tid >> 2, skg = (tid & 3) * 8;   // A staging: 64 rows x 4 chunks

    float accA[2][4][4], accB[2][4][4];
#pragma unroll
    for (int i = 0; i < 2; i++)
#pragma unroll
        for (int j = 0; j < 4; j++)
#pragma unroll
            for (int k = 0; k < 4; k++) { accA[i][j][k] = 0.f; accB[i][j][k] = 0.f; }

    // ---------------- phase 1 ----------------
    float4 u0, u1;
    auto load_x = [&](int t) {
        const int k = t * 32 + skg;
        const float* p = x + (size_t)(m0 + srow) * D_IN + k;
        u0 = *(const float4*)p;
        u1 = (k + 4 < D_IN) ? *(const float4*)(p + 4) : make_float4(0.f, 0.f, 0.f, 0.f);
    };
    auto store_A = [&](int buf) {
        char* Abp = smem + buf * BUF1;
        float v[8] = {u0.x, u0.y, u0.z, u0.w, u1.x, u1.y, u1.z, u1.w};
        __align__(16) __half h0[8], h1[8];
#pragma unroll
        for (int j = 0; j < 8; j++) split2(v[j] * 32.f, h0[j], h1[j]);
        char* d = Abp + srow * ROWB + skg * 2;
        *(uint4*)(d + 0 * CSTA) = *(uint4*)h0;
        *(uint4*)(d + 1 * CSTA) = *(uint4*)h1;
    };
    auto issue_B = [&](int t, int buf) {
        const int k0 = t * 32;
        const uint32_t Bb = sb + (uint32_t)(buf * BUF1 + ATILE_A);
#pragma unroll
        for (int c = 0; c < 2; c++)
#pragma unroll
            for (int i = 0; i < 2; i++) {
                int idx = tid + i * 256;
                int n = idx >> 2, ch = idx & 3;
                cpa16(Bb + (uint32_t)(c * CSTB + n * ROWB + ch * 16),
                      &g_wsplit[c][n][k0 + ch * 8]);
            }
    };

    load_x(0);
    store_A(0);
    issue_B(0, 0);
    cpa_wait_all();
    __syncthreads();

    for (int t = 0; t < 22; t++) {
        const bool more = (t + 1) < 22;
        if (more) {
            load_x(t + 1);
            issue_B(t + 1, (t + 1) & 1);
        }
        const uint32_t base = sb + (uint32_t)((t & 1) * BUF1);
        tile_mma(accA, accB, base, base + ATILE_A, a_lane, b_lane);
        if (more) store_A((t + 1) & 1);
        cpa_wait_all();
        __syncthreads();
    }

    // ---------------- phase-2 B staging ----------------
    auto stage_B2 = [&](int l, int kt, int buf) {
        const int k0 = kt * 32;
        const uint32_t Bb = sb + (uint32_t)(B2OFF + buf * BTILE);
#pragma unroll
        for (int c = 0; c < 2; c++)
#pragma unroll
            for (int i = 0; i < 2; i++) {
                int idx = tid + i * 256;
                int n = idx >> 2, ch = idx & 3;
                cpa16(Bb + (uint32_t)(c * CSTB + n * ROWB + ch * 16),
                      &g_asplit[c][l][n][k0 + ch * 8]);
            }
    };
    stage_B2(0, 0, 0);

    // ---------------- epilogue 1: split inp into phase-2 A layout ----------------
    {
        const float inv = 1.0f / 1024.0f;
#pragma unroll
        for (int mf = 0; mf < 2; mf++) {
            const int row0 = wm * 32 + mf * 16 + (lane >> 2);  // local row 0..63
#pragma unroll
            for (int nf = 0; nf < 4; nf++) {
                const int col = wn * 32 + nf * 8 + (lane & 3) * 2;
                const int kt = col >> 5, kk = col & 31;
                char* base = smem + kt * ATILE_A + kk * 2;
                const float bb0 = b_in[col], bb1 = b_in[col + 1];
#pragma unroll
                for (int hrow = 0; hrow < 2; hrow++) {
                    const int row = row0 + hrow * 8;
                    float va = (accA[mf][nf][hrow * 2 + 0] + accB[mf][nf][hrow * 2 + 0]) * inv + bb0;
                    float vb = (accA[mf][nf][hrow * 2 + 1] + accB[mf][nf][hrow * 2 + 1]) * inv + bb1;
                    va *= 32.f; vb *= 32.f;
                    __half a0, a1, b0, b1;
                    split2(va, a0, a1);
                    split2(vb, b0, b1);
                    char* d = base + row * ROWB;
                    *(__half2*)(d + 0 * CSTA) = __halves2half2(a0, b0);
                    *(__half2*)(d + 1 * CSTA) = __halves2half2(a1, b1);
                }
            }
        }
    }
    cpa_wait_all();
    __syncthreads();

    // ---------------- phase 2: 4 layers x 4 k-tiles ----------------
#pragma unroll
    for (int i = 0; i < 2; i++)
#pragma unroll
        for (int j = 0; j < 4; j++)
#pragma unroll
            for (int k = 0; k < 4; k++) { accA[i][j][k] = 0.f; accB[i][j][k] = 0.f; }

    const float inv = 1.0f / 1024.0f;
    for (int s = 0; s < 16; s++) {
        const int l = s >> 2, kt = s & 3;
        if (s + 1 < 16) stage_B2((s + 1) >> 2, (s + 1) & 3, (s + 1) & 1);
        tile_mma(accA, accB, sb + (uint32_t)(kt * ATILE_A),
                 sb + (uint32_t)(B2OFF + (s & 1) * BTILE), a_lane, b_lane);
        if (kt == 3) {
            float* dst = g_xs + (size_t)l * M_TOTAL * HID;
#pragma unroll
            for (int mf = 0; mf < 2; mf++) {
                const int row0 = m0 + wm * 32 + mf * 16 + (lane >> 2);
#pragma unroll
                for (int nf = 0; nf < 4; nf++) {
                    const int col = wn * 32 + nf * 8 + (lane & 3) * 2;
                    const float bb0 = Abias[l * HID + col];
                    const float bb1 = Abias[l * HID + col + 1];
                    *(float2*)(dst + (size_t)row0 * HID + col) =
                        make_float2((accA[mf][nf][0] + accB[mf][nf][0]) * inv + bb0,
                                    (accA[mf][nf][1] + accB[mf][nf][1]) * inv + bb1);
                    *(float2*)(dst + (size_t)(row0 + 8) * HID + col) =
                        make_float2((accA[mf][nf][2] + accB[mf][nf][2]) * inv + bb0,
                                    (accA[mf][nf][3] + accB[mf][nf][3]) * inv + bb1);
                }
            }
#pragma unroll
            for (int i = 0; i < 2; i++)
#pragma unroll
                for (int j = 0; j < 4; j++)
#pragma unroll
                    for (int k = 0; k < 4; k++) { accA[i][j][k] = 0.f; accB[i][j][k] = 0.f; }
        }
        cpa_wait_all();
        __syncthreads();
    }
}

// ============================================================
// Sequential LIF scan. block=(b,l), thread=h.
// ============================================================
__global__ void scan_kernel(const float* __restrict__ mem0,
                            const float* __restrict__ thr,
                            const float* __restrict__ decay,
                            const float* __restrict__ rstv,
                            float* __restrict__ dout) {
    const int b = blockIdx.x;
    const int l = blockIdx.y;
    const int h = threadIdx.x;

    const float* xp = g_xs + (size_t)l * M_TOTAL * HID + (size_t)b * T_STEPS * HID + h;
    float mem = mem0[(l * BATCH + b) * HID + h];
    float spk = 0.f, rate = 0.f;
    const float th = thr[h], dc = decay[h], rs = rstv[h];
    const bool last = (l == 3);

    float* mo = dout + MEM_OFF + (size_t)b * (T_STEPS + 1) * HID + h;
    float* so = dout + SPK_OFF + (size_t)b * (T_STEPS + 1) * HID + h;
    if (last) { mo[0] = mem; so[0] = 0.f; }

    for (int t = 0; t < T_STEPS; t += 10) {
        float v[10];
#pragma unroll
        for (int j = 0; j < 10; j++) v[j] = xp[(size_t)(t + j) * HID];
#pragma unroll
        for (int j = 0; j < 10; j++) {
            mem = rs * spk + mem * dc * (1.f - spk) + v[j];
            spk = (mem - th > 0.f) ? 1.f : 0.f;
            rate += spk;
            if (last) {
                mo[(size_t)(t + j + 1) * HID] = mem;
                so[(size_t)(t + j + 1) * HID] = spk;
            }
        }
    }
    g_rates[(l * BATCH + b) * HID + h] = rate * (1.f / 300.f);
}

// ============================================================
// Head: block per batch, 640 threads; fc_w pre-transposed.
// ============================================================
__global__ __launch_bounds__(640) void head_kernel(const float* __restrict__ fc_b,
                                                   const float* __restrict__ w_out,
                                                   const float* __restrict__ b_out,
                                                   float* __restrict__ dout) {
    const int b = blockIdx.x;
    const int tid = threadIdx.x;
    __shared__ float rs[512];
    __shared__ float cat[512];

    if (tid < 512) {
        int l = tid >> 7, h = tid & 127;
        rs[tid] = g_rates[(l * BATCH + b) * HID + h];
    }
    __syncthreads();

    if (tid < 512) {
        int l = tid >> 7, h = tid & 127;
        const float* W = &g_fcT[l][h][0];
        const float* rr = &rs[l * HID];
        float a0 = 0.f, a1 = 0.f, a2 = 0.f, a3 = 0.f;
#pragma unroll
        for (int k = 0; k < HID; k += 4) {
            float4 w4 = *(const float4*)(W + k);
            a0 += rr[k + 0] * w4.x;
            a1 += rr[k + 1] * w4.y;
            a2 += rr[k + 2] * w4.z;
            a3 += rr[k + 3] * w4.w;
        }
        float acc = ((a0 + a1) + (a2 + a3)) + fc_b[l * HID + h];
        cat[tid] = fmaxf(acc, 0.f);
    }
    __syncthreads();

    const int w = tid >> 5, lane = tid & 31;
    if (w < OUTD) {
        float acc = 0.f;
#pragma unroll
        for (int k = lane; k < 512; k += 32) acc += cat[k] * w_out[(size_t)k * OUTD + w];
#pragma unroll
        for (int off = 16; off; off >>= 1) acc += __shfl_down_sync(0xffffffffu, acc, off);
        if (lane == 0) dout[OUT_OFF + b * OUTD + w] = acc + b_out[w];
    }
}

// ============================================================
extern "C" void kernel_launch(void* const* d_in, const int* in_sizes, int n_in,
                              void* d_out, int out_size) {
    const float* x     = (const float*)d_in[0];
    const float* w_in  = (const float*)d_in[1];
    const float* b_in  = (const float*)d_in[2];
    const float* A_w   = (const float*)d_in[3];
    const float* A_b   = (const float*)d_in[4];
    const float* fc_w  = (const float*)d_in[5];
    const float* fc_b  = (const float*)d_in[6];
    const float* w_out = (const float*)d_in[7];
    const float* b_out = (const float*)d_in[8];
    const float* thr   = (const float*)d_in[9];
    const float* decay = (const float*)d_in[10];
    const float* rst   = (const float*)d_in[11];
    const float* mem0  = (const float*)d_in[12];
    float* out = (float*)d_out;

    cudaFuncSetAttribute(gemm_fused, cudaFuncAttributeMaxDynamicSharedMemorySize, FUSED_SMEM);

    // gemm_fused kept at launch index 3 for ncu capture
    norm_kernel<<<1, 1024>>>(A_w, out);
    presplit_w<<<(HID * KPAD + 255) / 256, 256>>>(w_in);
    presplit_A<<<(LAYERS * HID * HID + 255) / 256, 256>>>(A_w, fc_w);
    gemm_fused<<<M_TOTAL / 64, 256, FUSED_SMEM>>>(x, b_in, A_b);

    dim3 g3(BATCH, LAYERS);
    scan_kernel<<<g3, 128>>>(mem0, thr, decay, rst, out);

    head_kernel<<<BATCH, 640>>>(fc_b, w_out, b_out, out);
}

// round 15
// speedup vs baseline: 1.1773x; 1.0934x over previous
#include <cuda_runtime.h>
#include <cuda_fp16.h>
#include <cstdint>

// ---------------- problem constants ----------------
#define T_STEPS 300
#define BATCH   256
#define HID     128
#define D_IN    700
#define KPAD    704
#define LAYERS  4
#define OUTD    20
#define M_TOTAL (T_STEPS * BATCH)   // 76800

#define OUT_OFF  0
#define MEM_OFF  (BATCH * OUTD)
#define SPK_OFF  (MEM_OFF + BATCH * (T_STEPS + 1) * HID)
#define NORM_OFF (SPK_OFF + BATCH * (T_STEPS + 1) * HID)

// ---------------- scratch (device globals; no allocations) ----------------
__device__ float g_xs[(size_t)LAYERS * M_TOTAL * HID];
__device__ float g_rates[LAYERS * BATCH * HID];
// presplit weights (scaled x32), 2 fp16 comps, [comp][n][k]
__device__ __align__(16) __half g_wsplit[2][HID][KPAD];
__device__ __align__(16) __half g_asplit[2][LAYERS][HID][HID];
__device__ __align__(16) float g_fcT[LAYERS][HID][HID];

// ---------------- smem tile geometry (BK=64 staging) ----------------
#define ROWB    80
#define CSTRIDE (128 * ROWB)       // 10240 per comp per 32-k tile
#define ATILE   (2 * CSTRIDE)      // 20480: one 2-comp operand tile (32 k)
// stage buffer (64 k): [A_sub0, A_sub1, B_sub0, B_sub1]
#define SB_A0   0
#define SB_A1   ATILE
#define SB_B0   (2 * ATILE)
#define SB_B1   (3 * ATILE)
#define SBUF    (4 * ATILE)        // 81920
// phase-2: A-resident 4 kt at kt*ATILE (buffer-0 region);
//          B2 double buffer (2 tiles each) overlays buffer-1 region
#define B2BASE  SBUF               // 81920
#define FUSED_SMEM (2 * SBUF)      // 163840

// ---------------- helpers ----------------
__device__ __forceinline__ uint32_t smem_u32(const void* p) {
    uint32_t a;
    asm("{ .reg .u64 t; cvta.to.shared.u64 t, %1; cvt.u32.u64 %0, t; }" : "=r"(a) : "l"(p));
    return a;
}
__device__ __forceinline__ void ldsm4(uint32_t* d, uint32_t addr) {
    asm volatile("ldmatrix.sync.aligned.m8n8.x4.shared.b16 {%0,%1,%2,%3}, [%4];"
                 : "=r"(d[0]), "=r"(d[1]), "=r"(d[2]), "=r"(d[3]) : "r"(addr));
}
__device__ __forceinline__ void mma16816(float* d, const uint32_t* a, const uint32_t* b) {
    asm volatile(
        "mma.sync.aligned.m16n8k16.row.col.f32.f16.f16.f32 "
        "{%0,%1,%2,%3}, {%4,%5,%6,%7}, {%8,%9}, {%0,%1,%2,%3};"
        : "+f"(d[0]), "+f"(d[1]), "+f"(d[2]), "+f"(d[3])
        : "r"(a[0]), "r"(a[1]), "r"(a[2]), "r"(a[3]), "r"(b[0]), "r"(b[1]));
}
__device__ __forceinline__ void cpa16(uint32_t s, const void* g) {
    asm volatile("cp.async.cg.shared.global [%0], [%1], 16;" :: "r"(s), "l"(g));
}
__device__ __forceinline__ void cpa_wait_all() {
    asm volatile("cp.async.wait_all;" ::: "memory");
}
// 2-way fp16 split: residual <= 2^-25 |v| (fp32-class)
__device__ __forceinline__ void split2(float v, __half& c0, __half& c1) {
    c0 = __float2half_rn(v);
    c1 = __float2half_rn(v - __half2float(c0));
}

// ============================================================
// A_norm = sum |A_w|
// ============================================================
__global__ __launch_bounds__(1024) void norm_kernel(const float* __restrict__ Aw,
                                                    float* __restrict__ dout) {
    __shared__ float s[1024];
    float acc = 0.f;
    const float4* A4 = (const float4*)Aw;
    const int N4 = LAYERS * HID * HID / 4;
    for (int i = threadIdx.x; i < N4; i += 1024) {
        float4 v = A4[i];
        acc += fabsf(v.x) + fabsf(v.y) + fabsf(v.z) + fabsf(v.w);
    }
    s[threadIdx.x] = acc;
    __syncthreads();
    for (int st = 512; st > 0; st >>= 1) {
        if (threadIdx.x < st) s[threadIdx.x] += s[threadIdx.x + st];
        __syncthreads();
    }
    if (threadIdx.x == 0) dout[NORM_OFF] = s[0];
}

// ============================================================
// presplit_w: w_in -> 2 fp16 comps (x32), [n][k]
// ============================================================
__global__ __launch_bounds__(256) void presplit_w(const float* __restrict__ w_in) {
    int i = blockIdx.x * 256 + threadIdx.x;
    if (i < HID * KPAD) {
        int n = i / KPAD, k = i % KPAD;
        float v = (k < D_IN) ? w_in[(size_t)k * HID + n] * 32.f : 0.f;
        __half a, b;
        split2(v, a, b);
        g_wsplit[0][n][k] = a; g_wsplit[1][n][k] = b;
    }
}

// ============================================================
// presplit_A: A_w 2-comp split + fc_w transpose
// ============================================================
__global__ __launch_bounds__(256) void presplit_A(const float* __restrict__ Aw,
                                                  const float* __restrict__ fc_w) {
    int i = blockIdx.x * 256 + threadIdx.x;
    if (i < LAYERS * HID * HID) {
        int l = i >> 14, rem = i & 16383, n = rem >> 7, k = rem & 127;
        float v = Aw[(size_t)l * HID * HID + (size_t)k * HID + n] * 32.f;
        __half a, b;
        split2(v, a, b);
        g_asplit[0][l][n][k] = a; g_asplit[1][l][n][k] = b;
        g_fcT[l][n][k] = fc_w[(size_t)l * HID * HID + (size_t)k * HID + n];
    }
}

// ============================================================
// MMA core (warp tile 32x32), 3 passes:
//   accA += a0*b0 ; accB += a0*b1 + a1*b0
// ============================================================
__device__ __forceinline__ void tile_mma(float (&accA)[2][4][4], float (&accB)[2][4][4],
                                         uint32_t Ab, uint32_t Bb,
                                         uint32_t a_lane, uint32_t b_lane) {
#pragma unroll
    for (int ks = 0; ks < 2; ks++) {
        uint32_t bf[2][4][2];
#pragma unroll
        for (int c = 0; c < 2; c++)
#pragma unroll
            for (int np = 0; np < 2; np++) {
                uint32_t r4[4];
                ldsm4(r4, Bb + (uint32_t)(c * CSTRIDE + np * 16 * ROWB + ks * 32) + b_lane);
                bf[c][np * 2 + 0][0] = r4[0]; bf[c][np * 2 + 0][1] = r4[1];
                bf[c][np * 2 + 1][0] = r4[2]; bf[c][np * 2 + 1][1] = r4[3];
            }
        uint32_t af[2][4];
#pragma unroll
        for (int mf = 0; mf < 2; mf++)
            ldsm4(af[mf], Ab + (uint32_t)(0 * CSTRIDE + mf * 16 * ROWB + ks * 32) + a_lane);
#pragma unroll
        for (int mf = 0; mf < 2; mf++)
#pragma unroll
            for (int nf = 0; nf < 4; nf++) mma16816(accA[mf][nf], af[mf], bf[0][nf]);
#pragma unroll
        for (int mf = 0; mf < 2; mf++)
#pragma unroll
            for (int nf = 0; nf < 4; nf++) mma16816(accB[mf][nf], af[mf], bf[1][nf]);
#pragma unroll
        for (int mf = 0; mf < 2; mf++)
            ldsm4(af[mf], Ab + (uint32_t)(1 * CSTRIDE + mf * 16 * ROWB + ks * 32) + a_lane);
#pragma unroll
        for (int mf = 0; mf < 2; mf++)
#pragma unroll
            for (int nf = 0; nf < 4; nf++) mma16816(accB[mf][nf], af[mf], bf[0][nf]);
    }
}

// ============================================================
// FUSED GEMM, grid=600, 512 threads, BK=64 staging (1 barrier / 64 k):
//   phase 1: inp = x @ w_in + b_in (11 stages of 2 k-subtiles)
//   epilogue: split2(inp*32) direct to phase-2 smem A layout
//   phase 2: xs[l] = inp @ A_w[l] + A_b[l], 8 stages of 2 k-subtiles
// mma order per accumulator identical to R12 -> bit-identical outputs.
// ============================================================
__global__ __launch_bounds__(512, 1) void gemm_fused(const float* __restrict__ x,
                                                     const float* __restrict__ b_in,
                                                     const float* __restrict__ Abias) {
    extern __shared__ char smem[];
    const uint32_t sb = smem_u32(smem);
    const int tid = threadIdx.x, lane = tid & 31, wid = tid >> 5;
    const int wm = wid & 3, wn = wid >> 2;
    const int m0 = blockIdx.x * 128;
    const int q = lane >> 3, r = lane & 7;
    const uint32_t a_lane = (uint32_t)((wm * 32 + (q & 1) * 8 + r) * ROWB + ((q >> 1) * 8) * 2);
    const uint32_t b_lane = (uint32_t)((wn * 32 + (q >> 1) * 8 + r) * ROWB + ((q & 1) * 8) * 2);
    const int srow = tid >> 2, skg = (tid & 3) * 8;

    float accA[2][4][4], accB[2][4][4];
#pragma unroll
    for (int i = 0; i < 2; i++)
#pragma unroll
        for (int j = 0; j < 4; j++)
#pragma unroll
            for (int k = 0; k < 4; k++) { accA[i][j][k] = 0.f; accB[i][j][k] = 0.f; }

    // ---------------- phase 1 ----------------
    float4 u0, u1;
    auto load_x = [&](int t) {
        const int k = t * 32 + skg;
        const float* p = x + (size_t)(m0 + srow) * D_IN + k;
        u0 = *(const float4*)p;
        u1 = (k + 4 < D_IN) ? *(const float4*)(p + 4) : make_float4(0.f, 0.f, 0.f, 0.f);
    };
    auto store_A = [&](int buf, int slot) {
        char* Abp = smem + buf * SBUF + slot * ATILE;
        float v[8] = {u0.x, u0.y, u0.z, u0.w, u1.x, u1.y, u1.z, u1.w};
        __align__(16) __half h0[8], h1[8];
#pragma unroll
        for (int j = 0; j < 8; j++) split2(v[j] * 32.f, h0[j], h1[j]);
        char* d = Abp + srow * ROWB + skg * 2;
        *(uint4*)(d + 0 * CSTRIDE) = *(uint4*)h0;
        *(uint4*)(d + 1 * CSTRIDE) = *(uint4*)h1;
    };
    auto issue_B = [&](int t, int buf, int slot) {
        const int k0 = t * 32;
        const uint32_t Bb = sb + (uint32_t)(buf * SBUF + SB_B0 + slot * ATILE);
#pragma unroll
        for (int c = 0; c < 2; c++)
            cpa16(Bb + (uint32_t)(c * CSTRIDE + srow * ROWB + (tid & 3) * 16),
                  &g_wsplit[c][srow][k0 + skg]);
    };

    // prologue: stage 0 (tiles 0, 1)
    load_x(0); store_A(0, 0);
    load_x(1); store_A(0, 1);
    issue_B(0, 0, 0); issue_B(1, 0, 1);
    cpa_wait_all();
    __syncthreads();

    for (int s = 0; s < 11; s++) {
        const int buf = s & 1, nb = buf ^ 1;
        const bool more = s < 10;
        const uint32_t base = sb + (uint32_t)(buf * SBUF);
        if (more) load_x(2 * s + 2);
        tile_mma(accA, accB, base + SB_A0, base + SB_B0, a_lane, b_lane);
        if (more) { store_A(nb, 0); load_x(2 * s + 3); }
        tile_mma(accA, accB, base + SB_A1, base + SB_B1, a_lane, b_lane);
        if (more) {
            store_A(nb, 1);
            issue_B(2 * s + 2, nb, 0);
            issue_B(2 * s + 3, nb, 1);
        }
        cpa_wait_all();
        __syncthreads();
    }

    // ---------------- phase-2 B staging (2 k-tiles per stage) ----------------
    auto stage_B2 = [&](int p, int bufq) {
        const int l = p >> 1, kb = (p & 1) * 2;
        const uint32_t Bb = sb + (uint32_t)(B2BASE + bufq * (2 * ATILE));
#pragma unroll
        for (int sub = 0; sub < 2; sub++) {
            const int k0 = (kb + sub) * 32;
#pragma unroll
            for (int c = 0; c < 2; c++)
                cpa16(Bb + (uint32_t)(sub * ATILE + c * CSTRIDE + srow * ROWB + (tid & 3) * 16),
                      &g_asplit[c][l][srow][k0 + skg]);
        }
    };
    stage_B2(0, 0);

    // ---------------- epilogue 1: split inp into phase-2 A layout ----------------
    {
        const float inv = 1.0f / 1024.0f;
#pragma unroll
        for (int mf = 0; mf < 2; mf++) {
            const int row0 = wm * 32 + mf * 16 + (lane >> 2);
#pragma unroll
            for (int nf = 0; nf < 4; nf++) {
                const int col = wn * 32 + nf * 8 + (lane & 3) * 2;
                const int kt = col >> 5, kk = col & 31;
                char* base = smem + kt * ATILE + kk * 2;
                const float bb0 = b_in[col], bb1 = b_in[col + 1];
#pragma unroll
                for (int hrow = 0; hrow < 2; hrow++) {
                    const int row = row0 + hrow * 8;
                    float va = (accA[mf][nf][hrow * 2 + 0] + accB[mf][nf][hrow * 2 + 0]) * inv + bb0;
                    float vb = (accA[mf][nf][hrow * 2 + 1] + accB[mf][nf][hrow * 2 + 1]) * inv + bb1;
                    va *= 32.f; vb *= 32.f;
                    __half a0, a1, b0, b1;
                    split2(va, a0, a1);
                    split2(vb, b0, b1);
                    char* d = base + row * ROWB;
                    *(__half2*)(d + 0 * CSTRIDE) = __halves2half2(a0, b0);
                    *(__half2*)(d + 1 * CSTRIDE) = __halves2half2(a1, b1);
                }
            }
        }
    }
    cpa_wait_all();
    __syncthreads();

    // ---------------- phase 2: 8 stages (layer, kt-pair) ----------------
#pragma unroll
    for (int i = 0; i < 2; i++)
#pragma unroll
        for (int j = 0; j < 4; j++)
#pragma unroll
            for (int k = 0; k < 4; k++) { accA[i][j][k] = 0.f; accB[i][j][k] = 0.f; }

    const float inv = 1.0f / 1024.0f;
    for (int p = 0; p < 8; p++) {
        const int l = p >> 1, kb = (p & 1) * 2;
        const uint32_t Bb = sb + (uint32_t)(B2BASE + (p & 1) * (2 * ATILE));
        if (p + 1 < 8) stage_B2(p + 1, (p + 1) & 1);
        tile_mma(accA, accB, sb + (uint32_t)((kb + 0) * ATILE), Bb + 0, a_lane, b_lane);
        tile_mma(accA, accB, sb + (uint32_t)((kb + 1) * ATILE), Bb + ATILE, a_lane, b_lane);
        if (p & 1) {
            float* dst = g_xs + (size_t)l * M_TOTAL * HID;
#pragma unroll
            for (int mf = 0; mf < 2; mf++) {
                const int row0 = m0 + wm * 32 + mf * 16 + (lane >> 2);
#pragma unroll
                for (int nf = 0; nf < 4; nf++) {
                    const int col = wn * 32 + nf * 8 + (lane & 3) * 2;
                    const float bb0 = Abias[l * HID + col];
                    const float bb1 = Abias[l * HID + col + 1];
                    *(float2*)(dst + (size_t)row0 * HID + col) =
                        make_float2((accA[mf][nf][0] + accB[mf][nf][0]) * inv + bb0,
                                    (accA[mf][nf][1] + accB[mf][nf][1]) * inv + bb1);
                    *(float2*)(dst + (size_t)(row0 + 8) * HID + col) =
                        make_float2((accA[mf][nf][2] + accB[mf][nf][2]) * inv + bb0,
                                    (accA[mf][nf][3] + accB[mf][nf][3]) * inv + bb1);
                }
            }
#pragma unroll
            for (int i = 0; i < 2; i++)
#pragma unroll
                for (int j = 0; j < 4; j++)
#pragma unroll
                    for (int k = 0; k < 4; k++) { accA[i][j][k] = 0.f; accB[i][j][k] = 0.f; }
        }
        cpa_wait_all();
        __syncthreads();
    }
}

// ============================================================
// Sequential LIF scan. block=(b,l), thread=h.
// ============================================================
__global__ void scan_kernel(const float* __restrict__ mem0,
                            const float* __restrict__ thr,
                            const float* __restrict__ decay,
                            const float* __restrict__ rstv,
                            float* __restrict__ dout) {
    const int b = blockIdx.x;
    const int l = blockIdx.y;
    const int h = threadIdx.x;

    const float* xp = g_xs + (size_t)l * M_TOTAL * HID + (size_t)b * T_STEPS * HID + h;
    float mem = mem0[(l * BATCH + b) * HID + h];
    float spk = 0.f, rate = 0.f;
    const float th = thr[h], dc = decay[h], rs = rstv[h];
    const bool last = (l == 3);

    float* mo = dout + MEM_OFF + (size_t)b * (T_STEPS + 1) * HID + h;
    float* so = dout + SPK_OFF + (size_t)b * (T_STEPS + 1) * HID + h;
    if (last) { mo[0] = mem; so[0] = 0.f; }

    for (int t = 0; t < T_STEPS; t += 10) {
        float v[10];
#pragma unroll
        for (int j = 0; j < 10; j++) v[j] = xp[(size_t)(t + j) * HID];
#pragma unroll
        for (int j = 0; j < 10; j++) {
            mem = rs * spk + mem * dc * (1.f - spk) + v[j];
            spk = (mem - th > 0.f) ? 1.f : 0.f;
            rate += spk;
            if (last) {
                mo[(size_t)(t + j + 1) * HID] = mem;
                so[(size_t)(t + j + 1) * HID] = spk;
            }
        }
    }
    g_rates[(l * BATCH + b) * HID + h] = rate * (1.f / 300.f);
}

// ============================================================
// Head: block per batch, 640 threads; fc_w pre-transposed.
// ============================================================
__global__ __launch_bounds__(640) void head_kernel(const float* __restrict__ fc_b,
                                                   const float* __restrict__ w_out,
                                                   const float* __restrict__ b_out,
                                                   float* __restrict__ dout) {
    const int b = blockIdx.x;
    const int tid = threadIdx.x;
    __shared__ float rs[512];
    __shared__ float cat[512];

    if (tid < 512) {
        int l = tid >> 7, h = tid & 127;
        rs[tid] = g_rates[(l * BATCH + b) * HID + h];
    }
    __syncthreads();

    if (tid < 512) {
        int l = tid >> 7, h = tid & 127;
        const float* W = &g_fcT[l][h][0];
        const float* rr = &rs[l * HID];
        float a0 = 0.f, a1 = 0.f, a2 = 0.f, a3 = 0.f;
#pragma unroll
        for (int k = 0; k < HID; k += 4) {
            float4 w4 = *(const float4*)(W + k);
            a0 += rr[k + 0] * w4.x;
            a1 += rr[k + 1] * w4.y;
            a2 += rr[k + 2] * w4.z;
            a3 += rr[k + 3] * w4.w;
        }
        float acc = ((a0 + a1) + (a2 + a3)) + fc_b[l * HID + h];
        cat[tid] = fmaxf(acc, 0.f);
    }
    __syncthreads();

    const int w = tid >> 5, lane = tid & 31;
    if (w < OUTD) {
        float acc = 0.f;
#pragma unroll
        for (int k = lane; k < 512; k += 32) acc += cat[k] * w_out[(size_t)k * OUTD + w];
#pragma unroll
        for (int off = 16; off; off >>= 1) acc += __shfl_down_sync(0xffffffffu, acc, off);
        if (lane == 0) dout[OUT_OFF + b * OUTD + w] = acc + b_out[w];
    }
}

// ============================================================
extern "C" void kernel_launch(void* const* d_in, const int* in_sizes, int n_in,
                              void* d_out, int out_size) {
    const float* x     = (const float*)d_in[0];
    const float* w_in  = (const float*)d_in[1];
    const float* b_in  = (const float*)d_in[2];
    const float* A_w   = (const float*)d_in[3];
    const float* A_b   = (const float*)d_in[4];
    const float* fc_w  = (const float*)d_in[5];
    const float* fc_b  = (const float*)d_in[6];
    const float* w_out = (const float*)d_in[7];
    const float* b_out = (const float*)d_in[8];
    const float* thr   = (const float*)d_in[9];
    const float* decay = (const float*)d_in[10];
    const float* rst   = (const float*)d_in[11];
    const float* mem0  = (const float*)d_in[12];
    float* out = (float*)d_out;

    cudaFuncSetAttribute(gemm_fused, cudaFuncAttributeMaxDynamicSharedMemorySize, FUSED_SMEM);

    // gemm_fused kept at launch index 3 for ncu capture
    norm_kernel<<<1, 1024>>>(A_w, out);
    presplit_w<<<(HID * KPAD + 255) / 256, 256>>>(w_in);
    presplit_A<<<(LAYERS * HID * HID + 255) / 256, 256>>>(A_w, fc_w);
    gemm_fused<<<M_TOTAL / 128, 512, FUSED_SMEM>>>(x, b_in, A_b);

    dim3 g3(BATCH, LAYERS);
    scan_kernel<<<g3, 128>>>(mem0, thr, decay, rst, out);

    head_kernel<<<BATCH, 640>>>(fc_b, w_out, b_out, out);
}

// round 16
// speedup vs baseline: 1.2061x; 1.0245x over previous
#include <cuda_runtime.h>
#include <cuda_fp16.h>
#include <cstdint>

// ---------------- problem constants ----------------
#define T_STEPS 300
#define BATCH   256
#define HID     128
#define D_IN    700
#define KPAD    704
#define LAYERS  4
#define OUTD    20
#define M_TOTAL (T_STEPS * BATCH)   // 76800

#define OUT_OFF  0
#define MEM_OFF  (BATCH * OUTD)
#define SPK_OFF  (MEM_OFF + BATCH * (T_STEPS + 1) * HID)
#define NORM_OFF (SPK_OFF + BATCH * (T_STEPS + 1) * HID)

// ---------------- scratch (device globals; no allocations) ----------------
__device__ float g_xs[(size_t)LAYERS * M_TOTAL * HID];
__device__ float g_rates[LAYERS * BATCH * HID];
// presplit weights (scaled x32), 2 fp16 comps, [comp][n][k]
__device__ __align__(16) __half g_wsplit[2][HID][KPAD];
__device__ __align__(16) __half g_asplit[2][LAYERS][HID][HID];
__device__ __align__(16) float g_fcT[LAYERS][HID][HID];

// ---------------- smem tile geometry (BK=64 staging) ----------------
#define ROWB    80
#define CSTRIDE (128 * ROWB)       // 10240 per comp per 32-k tile
#define ATILE   (2 * CSTRIDE)      // 20480: one 2-comp operand tile (32 k)
// stage buffer (64 k): [A_sub0, A_sub1, B_sub0, B_sub1]
#define SB_A0   0
#define SB_A1   ATILE
#define SB_B0   (2 * ATILE)
#define SB_B1   (3 * ATILE)
#define SBUF    (4 * ATILE)        // 81920
#define B2BASE  SBUF               // 81920
#define FUSED_SMEM (2 * SBUF)      // 163840

// ---------------- helpers ----------------
__device__ __forceinline__ uint32_t smem_u32(const void* p) {
    uint32_t a;
    asm("{ .reg .u64 t; cvta.to.shared.u64 t, %1; cvt.u32.u64 %0, t; }" : "=r"(a) : "l"(p));
    return a;
}
__device__ __forceinline__ void ldsm4(uint32_t* d, uint32_t addr) {
    asm volatile("ldmatrix.sync.aligned.m8n8.x4.shared.b16 {%0,%1,%2,%3}, [%4];"
                 : "=r"(d[0]), "=r"(d[1]), "=r"(d[2]), "=r"(d[3]) : "r"(addr));
}
__device__ __forceinline__ void mma16816(float* d, const uint32_t* a, const uint32_t* b) {
    asm volatile(
        "mma.sync.aligned.m16n8k16.row.col.f32.f16.f16.f32 "
        "{%0,%1,%2,%3}, {%4,%5,%6,%7}, {%8,%9}, {%0,%1,%2,%3};"
        : "+f"(d[0]), "+f"(d[1]), "+f"(d[2]), "+f"(d[3])
        : "r"(a[0]), "r"(a[1]), "r"(a[2]), "r"(a[3]), "r"(b[0]), "r"(b[1]));
}
__device__ __forceinline__ void cpa16(uint32_t s, const void* g) {
    asm volatile("cp.async.cg.shared.global [%0], [%1], 16;" :: "r"(s), "l"(g));
}
__device__ __forceinline__ void cpa_wait_all() {
    asm volatile("cp.async.wait_all;" ::: "memory");
}
// 2-way fp16 split: residual <= 2^-25 |v| (fp32-class)
__device__ __forceinline__ void split2(float v, __half& c0, __half& c1) {
    c0 = __float2half_rn(v);
    c1 = __float2half_rn(v - __half2float(c0));
}

// ============================================================
// prep_kernel: one launch doing norm (block 0), presplit_w
// (blocks 1..352), presplit_A + fcT (blocks 353..608).
// ============================================================
__global__ __launch_bounds__(256) void prep_kernel(const float* __restrict__ Aw,
                                                   const float* __restrict__ w_in,
                                                   const float* __restrict__ fc_w,
                                                   float* __restrict__ dout) {
    const int bid = blockIdx.x;
    if (bid == 0) {
        __shared__ float s[256];
        float acc = 0.f;
        const float4* A4 = (const float4*)Aw;
        const int N4 = LAYERS * HID * HID / 4;
        for (int i = threadIdx.x; i < N4; i += 256) {
            float4 v = A4[i];
            acc += fabsf(v.x) + fabsf(v.y) + fabsf(v.z) + fabsf(v.w);
        }
        s[threadIdx.x] = acc;
        __syncthreads();
        for (int st = 128; st > 0; st >>= 1) {
            if (threadIdx.x < st) s[threadIdx.x] += s[threadIdx.x + st];
            __syncthreads();
        }
        if (threadIdx.x == 0) dout[NORM_OFF] = s[0];
    } else if (bid <= 352) {
        int i = (bid - 1) * 256 + threadIdx.x;   // 0 .. 90111 (= HID*KPAD)
        int n = i / KPAD, k = i % KPAD;
        float v = (k < D_IN) ? w_in[(size_t)k * HID + n] * 32.f : 0.f;
        __half a, b;
        split2(v, a, b);
        g_wsplit[0][n][k] = a; g_wsplit[1][n][k] = b;
    } else {
        int i = (bid - 353) * 256 + threadIdx.x; // 0 .. 65535 (= L*HID*HID)
        int l = i >> 14, rem = i & 16383, n = rem >> 7, k = rem & 127;
        float v = Aw[(size_t)l * HID * HID + (size_t)k * HID + n] * 32.f;
        __half a, b;
        split2(v, a, b);
        g_asplit[0][l][n][k] = a; g_asplit[1][l][n][k] = b;
        g_fcT[l][n][k] = fc_w[(size_t)l * HID * HID + (size_t)k * HID + n];
    }
}

// ============================================================
// MMA core (warp tile 32x32), 3 passes:
//   accA += a0*b0 ; accB += a0*b1 + a1*b0
// ============================================================
__device__ __forceinline__ void tile_mma(float (&accA)[2][4][4], float (&accB)[2][4][4],
                                         uint32_t Ab, uint32_t Bb,
                                         uint32_t a_lane, uint32_t b_lane) {
#pragma unroll
    for (int ks = 0; ks < 2; ks++) {
        uint32_t bf[2][4][2];
#pragma unroll
        for (int c = 0; c < 2; c++)
#pragma unroll
            for (int np = 0; np < 2; np++) {
                uint32_t r4[4];
                ldsm4(r4, Bb + (uint32_t)(c * CSTRIDE + np * 16 * ROWB + ks * 32) + b_lane);
                bf[c][np * 2 + 0][0] = r4[0]; bf[c][np * 2 + 0][1] = r4[1];
                bf[c][np * 2 + 1][0] = r4[2]; bf[c][np * 2 + 1][1] = r4[3];
            }
        uint32_t af[2][4];
#pragma unroll
        for (int mf = 0; mf < 2; mf++)
            ldsm4(af[mf], Ab + (uint32_t)(0 * CSTRIDE + mf * 16 * ROWB + ks * 32) + a_lane);
#pragma unroll
        for (int mf = 0; mf < 2; mf++)
#pragma unroll
            for (int nf = 0; nf < 4; nf++) mma16816(accA[mf][nf], af[mf], bf[0][nf]);
#pragma unroll
        for (int mf = 0; mf < 2; mf++)
#pragma unroll
            for (int nf = 0; nf < 4; nf++) mma16816(accB[mf][nf], af[mf], bf[1][nf]);
#pragma unroll
        for (int mf = 0; mf < 2; mf++)
            ldsm4(af[mf], Ab + (uint32_t)(1 * CSTRIDE + mf * 16 * ROWB + ks * 32) + a_lane);
#pragma unroll
        for (int mf = 0; mf < 2; mf++)
#pragma unroll
            for (int nf = 0; nf < 4; nf++) mma16816(accB[mf][nf], af[mf], bf[0][nf]);
    }
}

// ============================================================
// FUSED GEMM, grid=600, 512 threads, BK=64 staging.
// B cp.async for stage s+1 issued at the TOP of stage s (full mma cover).
// mma order per accumulator identical to R15 -> bit-identical outputs.
// ============================================================
__global__ __launch_bounds__(512, 1) void gemm_fused(const float* __restrict__ x,
                                                     const float* __restrict__ b_in,
                                                     const float* __restrict__ Abias) {
    extern __shared__ char smem[];
    const uint32_t sb = smem_u32(smem);
    const int tid = threadIdx.x, lane = tid & 31, wid = tid >> 5;
    const int wm = wid & 3, wn = wid >> 2;
    const int m0 = blockIdx.x * 128;
    const int q = lane >> 3, r = lane & 7;
    const uint32_t a_lane = (uint32_t)((wm * 32 + (q & 1) * 8 + r) * ROWB + ((q >> 1) * 8) * 2);
    const uint32_t b_lane = (uint32_t)((wn * 32 + (q >> 1) * 8 + r) * ROWB + ((q & 1) * 8) * 2);
    const int srow = tid >> 2, skg = (tid & 3) * 8;

    float accA[2][4][4], accB[2][4][4];
#pragma unroll
    for (int i = 0; i < 2; i++)
#pragma unroll
        for (int j = 0; j < 4; j++)
#pragma unroll
            for (int k = 0; k < 4; k++) { accA[i][j][k] = 0.f; accB[i][j][k] = 0.f; }

    // ---------------- phase 1 ----------------
    float4 u0, u1;
    auto load_x = [&](int t) {
        const int k = t * 32 + skg;
        const float* p = x + (size_t)(m0 + srow) * D_IN + k;
        u0 = *(const float4*)p;
        u1 = (k + 4 < D_IN) ? *(const float4*)(p + 4) : make_float4(0.f, 0.f, 0.f, 0.f);
    };
    auto store_A = [&](int buf, int slot) {
        char* Abp = smem + buf * SBUF + slot * ATILE;
        float v[8] = {u0.x, u0.y, u0.z, u0.w, u1.x, u1.y, u1.z, u1.w};
        __align__(16) __half h0[8], h1[8];
#pragma unroll
        for (int j = 0; j < 8; j++) split2(v[j] * 32.f, h0[j], h1[j]);
        char* d = Abp + srow * ROWB + skg * 2;
        *(uint4*)(d + 0 * CSTRIDE) = *(uint4*)h0;
        *(uint4*)(d + 1 * CSTRIDE) = *(uint4*)h1;
    };
    auto issue_B = [&](int t, int buf, int slot) {
        const int k0 = t * 32;
        const uint32_t Bb = sb + (uint32_t)(buf * SBUF + SB_B0 + slot * ATILE);
#pragma unroll
        for (int c = 0; c < 2; c++)
            cpa16(Bb + (uint32_t)(c * CSTRIDE + srow * ROWB + (tid & 3) * 16),
                  &g_wsplit[c][srow][k0 + skg]);
    };

    // prologue: stage 0 (tiles 0, 1)
    load_x(0); store_A(0, 0);
    load_x(1); store_A(0, 1);
    issue_B(0, 0, 0); issue_B(1, 0, 1);
    cpa_wait_all();
    __syncthreads();

    for (int s = 0; s < 11; s++) {
        const int buf = s & 1, nb = buf ^ 1;
        const bool more = s < 10;
        const uint32_t base = sb + (uint32_t)(buf * SBUF);
        if (more) {
            issue_B(2 * s + 2, nb, 0);   // hoisted: covered by both tile_mmas
            issue_B(2 * s + 3, nb, 1);
            load_x(2 * s + 2);
        }
        tile_mma(accA, accB, base + SB_A0, base + SB_B0, a_lane, b_lane);
        if (more) { store_A(nb, 0); load_x(2 * s + 3); }
        tile_mma(accA, accB, base + SB_A1, base + SB_B1, a_lane, b_lane);
        if (more) store_A(nb, 1);
        cpa_wait_all();
        __syncthreads();
    }

    // ---------------- phase-2 B staging (2 k-tiles per stage) ----------------
    auto stage_B2 = [&](int p, int bufq) {
        const int l = p >> 1, kb = (p & 1) * 2;
        const uint32_t Bb = sb + (uint32_t)(B2BASE + bufq * (2 * ATILE));
#pragma unroll
        for (int sub = 0; sub < 2; sub++) {
            const int k0 = (kb + sub) * 32;
#pragma unroll
            for (int c = 0; c < 2; c++)
                cpa16(Bb + (uint32_t)(sub * ATILE + c * CSTRIDE + srow * ROWB + (tid & 3) * 16),
                      &g_asplit[c][l][srow][k0 + skg]);
        }
    };
    stage_B2(0, 0);

    // ---------------- epilogue 1: split inp into phase-2 A layout ----------------
    {
        const float inv = 1.0f / 1024.0f;
#pragma unroll
        for (int mf = 0; mf < 2; mf++) {
            const int row0 = wm * 32 + mf * 16 + (lane >> 2);
#pragma unroll
            for (int nf = 0; nf < 4; nf++) {
                const int col = wn * 32 + nf * 8 + (lane & 3) * 2;
                const int kt = col >> 5, kk = col & 31;
                char* base = smem + kt * ATILE + kk * 2;
                const float bb0 = b_in[col], bb1 = b_in[col + 1];
#pragma unroll
                for (int hrow = 0; hrow < 2; hrow++) {
                    const int row = row0 + hrow * 8;
                    float va = (accA[mf][nf][hrow * 2 + 0] + accB[mf][nf][hrow * 2 + 0]) * inv + bb0;
                    float vb = (accA[mf][nf][hrow * 2 + 1] + accB[mf][nf][hrow * 2 + 1]) * inv + bb1;
                    va *= 32.f; vb *= 32.f;
                    __half a0, a1, b0, b1;
                    split2(va, a0, a1);
                    split2(vb, b0, b1);
                    char* d = base + row * ROWB;
                    *(__half2*)(d + 0 * CSTRIDE) = __halves2half2(a0, b0);
                    *(__half2*)(d + 1 * CSTRIDE) = __halves2half2(a1, b1);
                }
            }
        }
    }
    cpa_wait_all();
    __syncthreads();

    // ---------------- phase 2: 8 stages (layer, kt-pair) ----------------
#pragma unroll
    for (int i = 0; i < 2; i++)
#pragma unroll
        for (int j = 0; j < 4; j++)
#pragma unroll
            for (int k = 0; k < 4; k++) { accA[i][j][k] = 0.f; accB[i][j][k] = 0.f; }

    const float inv = 1.0f / 1024.0f;
    for (int p = 0; p < 8; p++) {
        const int l = p >> 1, kb = (p & 1) * 2;
        const uint32_t Bb = sb + (uint32_t)(B2BASE + (p & 1) * (2 * ATILE));
        if (p + 1 < 8) stage_B2(p + 1, (p + 1) & 1);
        tile_mma(accA, accB, sb + (uint32_t)((kb + 0) * ATILE), Bb + 0, a_lane, b_lane);
        tile_mma(accA, accB, sb + (uint32_t)((kb + 1) * ATILE), Bb + ATILE, a_lane, b_lane);
        if (p & 1) {
            float* dst = g_xs + (size_t)l * M_TOTAL * HID;
#pragma unroll
            for (int mf = 0; mf < 2; mf++) {
                const int row0 = m0 + wm * 32 + mf * 16 + (lane >> 2);
#pragma unroll
                for (int nf = 0; nf < 4; nf++) {
                    const int col = wn * 32 + nf * 8 + (lane & 3) * 2;
                    const float bb0 = Abias[l * HID + col];
                    const float bb1 = Abias[l * HID + col + 1];
                    *(float2*)(dst + (size_t)row0 * HID + col) =
                        make_float2((accA[mf][nf][0] + accB[mf][nf][0]) * inv + bb0,
                                    (accA[mf][nf][1] + accB[mf][nf][1]) * inv + bb1);
                    *(float2*)(dst + (size_t)(row0 + 8) * HID + col) =
                        make_float2((accA[mf][nf][2] + accB[mf][nf][2]) * inv + bb0,
                                    (accA[mf][nf][3] + accB[mf][nf][3]) * inv + bb1);
                }
            }
#pragma unroll
            for (int i = 0; i < 2; i++)
#pragma unroll
                for (int j = 0; j < 4; j++)
#pragma unroll
                    for (int k = 0; k < 4; k++) { accA[i][j][k] = 0.f; accB[i][j][k] = 0.f; }
        }
        cpa_wait_all();
        __syncthreads();
    }
}

// ============================================================
// Sequential LIF scan. block=(b,l), thread=h.
// ============================================================
__global__ void scan_kernel(const float* __restrict__ mem0,
                            const float* __restrict__ thr,
                            const float* __restrict__ decay,
                            const float* __restrict__ rstv,
                            float* __restrict__ dout) {
    const int b = blockIdx.x;
    const int l = blockIdx.y;
    const int h = threadIdx.x;

    const float* xp = g_xs + (size_t)l * M_TOTAL * HID + (size_t)b * T_STEPS * HID + h;
    float mem = mem0[(l * BATCH + b) * HID + h];
    float spk = 0.f, rate = 0.f;
    const float th = thr[h], dc = decay[h], rs = rstv[h];
    const bool last = (l == 3);

    float* mo = dout + MEM_OFF + (size_t)b * (T_STEPS + 1) * HID + h;
    float* so = dout + SPK_OFF + (size_t)b * (T_STEPS + 1) * HID + h;
    if (last) { mo[0] = mem; so[0] = 0.f; }

    for (int t = 0; t < T_STEPS; t += 10) {
        float v[10];
#pragma unroll
        for (int j = 0; j < 10; j++) v[j] = xp[(size_t)(t + j) * HID];
#pragma unroll
        for (int j = 0; j < 10; j++) {
            mem = rs * spk + mem * dc * (1.f - spk) + v[j];
            spk = (mem - th > 0.f) ? 1.f : 0.f;
            rate += spk;
            if (last) {
                mo[(size_t)(t + j + 1) * HID] = mem;
                so[(size_t)(t + j + 1) * HID] = spk;
            }
        }
    }
    g_rates[(l * BATCH + b) * HID + h] = rate * (1.f / 300.f);
}

// ============================================================
// Head: block per batch, 640 threads; fc_w pre-transposed.
// ============================================================
__global__ __launch_bounds__(640) void head_kernel(const float* __restrict__ fc_b,
                                                   const float* __restrict__ w_out,
                                                   const float* __restrict__ b_out,
                                                   float* __restrict__ dout) {
    const int b = blockIdx.x;
    const int tid = threadIdx.x;
    __shared__ float rs[512];
    __shared__ float cat[512];

    if (tid < 512) {
        int l = tid >> 7, h = tid & 127;
        rs[tid] = g_rates[(l * BATCH + b) * HID + h];
    }
    __syncthreads();

    if (tid < 512) {
        int l = tid >> 7, h = tid & 127;
        const float* W = &g_fcT[l][h][0];
        const float* rr = &rs[l * HID];
        float a0 = 0.f, a1 = 0.f, a2 = 0.f, a3 = 0.f;
#pragma unroll
        for (int k = 0; k < HID; k += 4) {
            float4 w4 = *(const float4*)(W + k);
            a0 += rr[k + 0] * w4.x;
            a1 += rr[k + 1] * w4.y;
            a2 += rr[k + 2] * w4.z;
            a3 += rr[k + 3] * w4.w;
        }
        float acc = ((a0 + a1) + (a2 + a3)) + fc_b[l * HID + h];
        cat[tid] = fmaxf(acc, 0.f);
    }
    __syncthreads();

    const int w = tid >> 5, lane = tid & 31;
    if (w < OUTD) {
        float acc = 0.f;
#pragma unroll
        for (int k = lane; k < 512; k += 32) acc += cat[k] * w_out[(size_t)k * OUTD + w];
#pragma unroll
        for (int off = 16; off; off >>= 1) acc += __shfl_down_sync(0xffffffffu, acc, off);
        if (lane == 0) dout[OUT_OFF + b * OUTD + w] = acc + b_out[w];
    }
}

// ============================================================
extern "C" void kernel_launch(void* const* d_in, const int* in_sizes, int n_in,
                              void* d_out, int out_size) {
    const float* x     = (const float*)d_in[0];
    const float* w_in  = (const float*)d_in[1];
    const float* b_in  = (const float*)d_in[2];
    const float* A_w   = (const float*)d_in[3];
    const float* A_b   = (const float*)d_in[4];
    const float* fc_w  = (const float*)d_in[5];
    const float* fc_b  = (const float*)d_in[6];
    const float* w_out = (const float*)d_in[7];
    const float* b_out = (const float*)d_in[8];
    const float* thr   = (const float*)d_in[9];
    const float* decay = (const float*)d_in[10];
    const float* rst   = (const float*)d_in[11];
    const float* mem0  = (const float*)d_in[12];
    float* out = (float*)d_out;

    cudaFuncSetAttribute(gemm_fused, cudaFuncAttributeMaxDynamicSharedMemorySize, FUSED_SMEM);

    prep_kernel<<<609, 256>>>(A_w, w_in, fc_w, out);

    gemm_fused<<<M_TOTAL / 128, 512, FUSED_SMEM>>>(x, b_in, A_b);

    dim3 g3(BATCH, LAYERS);
    scan_kernel<<<g3, 128>>>(mem0, thr, decay, rst, out);

    head_kernel<<<BATCH, 640>>>(fc_b, w_out, b_out, out);
}